// round 14
// baseline (speedup 1.0000x reference)
#include <cuda_runtime.h>
#include <cuda_fp16.h>
#include <math.h>
#include <stdint.h>

#define NOBS 72000
#define NBUK 9000
#define LMAXX 8
#define DIM 256
#define NTOK 8
#define DH 32
#define DEPTH 8
#define FFND 1024
#define OUTD 2048
#define CLAT 512
#define NWELEM 7536640
#define MCHUNK 24000            // FFN L2-blocking chunk (49MB intermediate)

// ---------------- scratch (device globals; no allocation allowed) ----------
static __device__ __align__(16) float  g_trx[NOBS * DIM];
static __device__ __align__(16) __half g_ah [NOBS * FFND];
static __device__ __align__(16) __half g_bh [NOBS * DIM];
static __device__ __align__(16) __half g_ch [NOBS * DIM];
static __device__ __align__(16) __half g_kh [NOBS * DIM * DEPTH];
static __device__ __align__(16) __half g_vh [NOBS * DIM * DEPTH];
static __device__ __align__(16) __half g_wh [NWELEM];
static __device__ int g_cnt[NBUK];
static __device__ int g_row[NOBS];

// offsets (elements) into transposed half weight slab [N,K]
#define OFF_MLPW 0
#define OFF_WQ   196608
#define OFF_WK   720896
#define OFF_WV   1245184
#define OFF_WO   1769472
#define OFF_W1   2293760
#define OFF_W2   4390912
#define OFF_PROJ 6488064

__device__ __forceinline__ float gelu_tanh(float x) {
    float x3 = x * x * x;
    float t = tanhf(0.7978845608028654f * (x + 0.044715f * x3));
    return 0.5f * x * (1.0f + t);
}

__device__ __forceinline__ void mma_fp16(float* c, const uint32_t* a,
                                         uint32_t b0, uint32_t b1) {
    asm volatile(
        "mma.sync.aligned.m16n8k16.row.col.f32.f16.f16.f32 "
        "{%0,%1,%2,%3},{%4,%5,%6,%7},{%8,%9},{%0,%1,%2,%3};\n"
        : "+f"(c[0]), "+f"(c[1]), "+f"(c[2]), "+f"(c[3])
        : "r"(a[0]), "r"(a[1]), "r"(a[2]), "r"(a[3]), "r"(b0), "r"(b1));
}

__device__ __forceinline__ void ldsm_x4(uint32_t& r0, uint32_t& r1,
                                        uint32_t& r2, uint32_t& r3, uint32_t a) {
    asm volatile("ldmatrix.sync.aligned.m8n8.x4.shared.b16 {%0,%1,%2,%3}, [%4];"
                 : "=r"(r0), "=r"(r1), "=r"(r2), "=r"(r3) : "r"(a));
}

__device__ __forceinline__ void cp_async16(uint32_t saddr, const void* g, int srcB) {
    asm volatile("cp.async.cg.shared.global [%0], [%1], 16, %2;\n"
                 :: "r"(saddr), "l"(g), "r"(srcB));
}
__device__ __forceinline__ void cp_commit() {
    asm volatile("cp.async.commit_group;\n");
}
template <int N>
__device__ __forceinline__ void cp_wait() {
    asm volatile("cp.async.wait_group %0;\n" :: "n"(N));
}

// ---------------- FP16 tensor-core GEMM (ldmatrix + m16n8k16) ---------------
// C[M,N] = act(A[M,K] @ B[K,N] + bias) [+res] [gated]
// A: half [M,K] row-major. B: half TRANSPOSED [N,K] row-major.
// BM=128, BN=128, BK=64, 256 thr, 4(M)x2(N) warps, 3-stage cp.async.
#define ASTR_B 144                  // padded row stride: 128B data + 16B pad
#define TILE_HB (128 * ASTR_B)      // 18432 B per operand tile
#define STAGE_HB (2 * TILE_HB)      // 36864 B per stage
#define GEMM_SMEM_H (3 * STAGE_HB)  // 110592 B

__global__ __launch_bounds__(256, 2)
void k_gemm_h(const __half* __restrict__ A, const __half* __restrict__ B,
              const float* __restrict__ bias, const float* __restrict__ res,
              const int* __restrict__ gate,
              float* __restrict__ Cf, __half* __restrict__ Ch,
              int M, int N, int K, int act)
{
    extern __shared__ char smem[];
    const uint32_t sb = (uint32_t)__cvta_generic_to_shared(smem);
    const int tid = threadIdx.x, lane = tid & 31, warp = tid >> 5;
    const int wm = warp & 3, wn = warp >> 2;
    const int rowBase = blockIdx.y << 7, colBase = blockIdx.x << 7;

    float acc[2][8][4];
#pragma unroll
    for (int i = 0; i < 2; i++)
#pragma unroll
        for (int j = 0; j < 8; j++)
#pragma unroll
            for (int l = 0; l < 4; l++) acc[i][j][l] = 0.0f;

    auto load_stage = [&](int t, int s) {
        uint32_t dst = sb + s * STAGE_HB;
        const int kt = t << 6;
#pragma unroll
        for (int r = 0; r < 4; r++) {        // A: 128 rows x 8 chunks of 16B
            int f = tid + (r << 8);
            int row = f >> 3, c = f & 7;
            int gm = rowBase + row;
            cp_async16(dst + row * ASTR_B + c * 16,
                       A + (size_t)(gm < M ? gm : 0) * K + kt + c * 8,
                       gm < M ? 16 : 0);
        }
#pragma unroll
        for (int r = 0; r < 4; r++) {        // B: 128 n-rows x 8 chunks
            int f = tid + (r << 8);
            int row = f >> 3, c = f & 7;
            cp_async16(dst + TILE_HB + row * ASTR_B + c * 16,
                       B + (size_t)(colBase + row) * K + kt + c * 8, 16);
        }
        cp_commit();
    };

    const int li = lane & 7, lj = lane >> 3;
    const uint32_t aoff = (uint32_t)((wm * 32 + (lj & 1) * 8 + li) * ASTR_B
                                     + (lj >> 1) * 16);
    const uint32_t boff = (uint32_t)(TILE_HB + (wn * 64 + (lj >> 1) * 8 + li) * ASTR_B
                                     + (lj & 1) * 16);

    auto compute = [&](int s) {
        const uint32_t st = sb + s * STAGE_HB;
#pragma unroll
        for (int ks = 0; ks < 4; ks++) {      // 4 x k16
            uint32_t af[2][4];
            ldsm_x4(af[0][0], af[0][1], af[0][2], af[0][3], st + aoff + ks * 32);
            ldsm_x4(af[1][0], af[1][1], af[1][2], af[1][3],
                    st + aoff + 16 * ASTR_B + ks * 32);
#pragma unroll
            for (int g16 = 0; g16 < 4; g16++) {
                uint32_t b0, b1, b2, b3;
                ldsm_x4(b0, b1, b2, b3, st + boff + g16 * (16 * ASTR_B) + ks * 32);
                mma_fp16(acc[0][g16 * 2 + 0], af[0], b0, b1);
                mma_fp16(acc[1][g16 * 2 + 0], af[1], b0, b1);
                mma_fp16(acc[0][g16 * 2 + 1], af[0], b2, b3);
                mma_fp16(acc[1][g16 * 2 + 1], af[1], b2, b3);
            }
        }
    };

    const int T = K >> 6;
    load_stage(0, 0);
    if (T > 1) load_stage(1, 1);
    for (int t = 0; t < T; t++) {
        if (t + 1 < T) cp_wait<1>(); else cp_wait<0>();
        __syncthreads();
        if (t + 2 < T) load_stage(t + 2, (t + 2) % 3);
        compute(t % 3);
    }

    // ---------------- epilogue ----------------
#pragma unroll
    for (int mt = 0; mt < 2; mt++) {
#pragma unroll
        for (int hf = 0; hf < 2; hf++) {
            int gm = rowBase + wm * 32 + mt * 16 + (lane >> 2) + hf * 8;
            if (gm >= M) continue;
            bool gz = (gate && gate[gm] == 0);
#pragma unroll
            for (int nt = 0; nt < 8; nt++) {
                int gn = colBase + wn * 64 + nt * 8 + ((lane & 3) << 1);
                float cx = acc[mt][nt][hf * 2 + 0];
                float cy = acc[mt][nt][hf * 2 + 1];
                if (bias) {
                    float2 bv = *(const float2*)(bias + gn);
                    cx += bv.x; cy += bv.y;
                }
                if (act) { cx = gelu_tanh(cx); cy = gelu_tanh(cy); }
                if (res) {
                    float2 rv = *(const float2*)(res + (size_t)gm * N + gn);
                    cx += rv.x; cy += rv.y;
                }
                if (gz) { cx = 0.f; cy = 0.f; }
                if (Cf)
                    *(float2*)(Cf + (size_t)gm * N + gn) = make_float2(cx, cy);
                if (Ch)
                    *(__half2*)(Ch + (size_t)gm * N + gn) = __floats2half2_rn(cx, cy);
            }
        }
    }
}

// ---------------- layernorm: outputs half (feeds GEMM A) --------------------
__global__ void k_ln(const float* __restrict__ X, __half* __restrict__ Y,
                     const float* __restrict__ G, const float* __restrict__ Bb)
{
    int row  = blockIdx.x * 8 + (threadIdx.x >> 5);
    int lane = threadIdx.x & 31;
    const float* x = X + (size_t)row * DIM;
    float v[8];
    float s = 0.f;
#pragma unroll
    for (int r = 0; r < 8; r++) { v[r] = x[lane + (r << 5)]; s += v[r]; }
#pragma unroll
    for (int off = 16; off; off >>= 1) s += __shfl_xor_sync(0xffffffffu, s, off);
    float mean = s * (1.0f / 256.0f);
    float vs = 0.f;
#pragma unroll
    for (int r = 0; r < 8; r++) { float d = v[r] - mean; vs = fmaf(d, d, vs); }
#pragma unroll
    for (int off = 16; off; off >>= 1) vs += __shfl_xor_sync(0xffffffffu, vs, off);
    float inv = rsqrtf(vs * (1.0f / 256.0f) + 1e-5f);
#pragma unroll
    for (int r = 0; r < 8; r++) {
        int c = lane + (r << 5);
        Y[(size_t)row * DIM + c] = __float2half((v[r] - mean) * inv * G[c] + Bb[c]);
    }
}

// ---------------- per-bucket cross attention (half in / half out) -----------
__global__ void k_attn(const __half* __restrict__ Q, const __half* __restrict__ Kx,
                       const __half* __restrict__ V, __half* __restrict__ O,
                       int loff)
{
    __shared__ __align__(16) __half sQ[NTOK * DIM];
    __shared__ __align__(16) __half sK[LMAXX * DIM];
    __shared__ __align__(16) __half sV[LMAXX * DIM];
    int b = blockIdx.x;
    int tid = threadIdx.x;  // 64 threads
#pragma unroll
    for (int r = 0; r < 4; r++) {
        int idx = tid + r * 64;          // 0..255 uint4 slots
        int row = idx >> 5, c8 = idx & 31;
        ((uint4*)sQ)[idx] = *(const uint4*)(Q + (size_t)(b * 8 + row) * DIM + c8 * 8);
        ((uint4*)sK)[idx] = *(const uint4*)(Kx + (size_t)(b * 8 + row) * (DIM * DEPTH)
                                            + loff + c8 * 8);
        ((uint4*)sV)[idx] = *(const uint4*)(V + (size_t)(b * 8 + row) * (DIM * DEPTH)
                                            + loff + c8 * 8);
    }
    int cnt = g_cnt[b];
    __syncthreads();

    int h = tid >> 3, qi = tid & 7;
    const __half2* qp = (const __half2*)(sQ + qi * DIM + h * DH);
    float2 qr[DH / 2];
#pragma unroll
    for (int d = 0; d < DH / 2; d++) qr[d] = __half22float2(qp[d]);

    float sc[LMAXX];
    float mx = -1e30f;
#pragma unroll
    for (int j = 0; j < LMAXX; j++) {
        const __half2* kp = (const __half2*)(sK + j * DIM + h * DH);
        float s = 0.f;
#pragma unroll
        for (int d = 0; d < DH / 2; d++) {
            float2 kv = __half22float2(kp[d]);
            s = fmaf(qr[d].x, kv.x, s);
            s = fmaf(qr[d].y, kv.y, s);
        }
        s = s * 0.17677669529663689f;
        if (j >= cnt) s -= 1e9f;
        sc[j] = s;
        mx = fmaxf(mx, s);
    }
    float den = 0.f;
#pragma unroll
    for (int j = 0; j < LMAXX; j++) { sc[j] = expf(sc[j] - mx); den += sc[j]; }
    float inv = 1.0f / den;
    float o[DH];
#pragma unroll
    for (int d = 0; d < DH; d++) o[d] = 0.f;
#pragma unroll
    for (int j = 0; j < LMAXX; j++) {
        float a = sc[j] * inv;
        const __half2* vp = (const __half2*)(sV + j * DIM + h * DH);
#pragma unroll
        for (int d = 0; d < DH / 2; d++) {
            float2 vv = __half22float2(vp[d]);
            o[2 * d]     = fmaf(a, vv.x, o[2 * d]);
            o[2 * d + 1] = fmaf(a, vv.y, o[2 * d + 1]);
        }
    }
    __half* op = O + (size_t)(b * NTOK + qi) * DIM + h * DH;
#pragma unroll
    for (int d = 0; d < DH / 2; d++)
        ((__half2*)op)[d] = __floats2half2_rn(o[2 * d], o[2 * d + 1]);
}

// ---------------- dispatch helpers ------------------------------------------
__global__ void k_reset_cnt()
{
    int i = blockIdx.x * blockDim.x + threadIdx.x;
    if (i < NBUK) g_cnt[i] = 0;
}

__global__ void k_flatpos(const int* __restrict__ li)
{
    int i = blockIdx.x * blockDim.x + threadIdx.x;
    if (i >= NOBS) return;
    int d = li[3 * i], hh = li[3 * i + 1], w = li[3 * i + 2];
    int f = d * 1800 + hh * 60 + w;
    int pos = atomicAdd(&g_cnt[f], 1);
    g_row[i] = (pos < LMAXX) ? (f * LMAXX + pos) : -1;
}

__global__ void k_scatter(const __half* __restrict__ S)
{
    int wid  = (blockIdx.x * blockDim.x + threadIdx.x) >> 5;
    int lane = threadIdx.x & 31;
    if (wid >= NOBS) return;
    int dst = g_row[wid];
    if (dst < 0) return;
    ((uint4*)(g_ch + (size_t)dst * DIM))[lane] =
        ((const uint4*)(S + (size_t)wid * DIM))[lane];
}

__global__ void k_init_trx(const float* __restrict__ bg)
{
    int idx = blockIdx.x * blockDim.x + threadIdx.x;
    if (idx >= NOBS * DIM / 4) return;
    int row = idx >> 6;
    int t   = row & 7;
    int c4  = idx & 63;
    ((float4*)g_trx)[idx] = ((const float4*)bg)[t * 64 + c4];
}

// ---------------- fp32 -> half (input x) -------------------------------------
__global__ void k_tohalf(const float4* __restrict__ s, __half* __restrict__ d, int n4)
{
    int i = blockIdx.x * blockDim.x + threadIdx.x;
    if (i >= n4) return;
    float4 v = s[i];
    ((__half2*)d)[2 * i]     = __floats2half2_rn(v.x, v.y);
    ((__half2*)d)[2 * i + 1] = __floats2half2_rn(v.z, v.w);
}

// ---------------- weight transpose+convert: W[K,N] fp32 -> WT[N,K] half -----
__global__ void k_wt(const float* __restrict__ W, __half* __restrict__ T,
                     int K, int N)
{
    __shared__ float tile[32][33];
    size_t boff = (size_t)blockIdx.z * K * N;
    int n0 = blockIdx.x * 32, k0 = blockIdx.y * 32;
#pragma unroll
    for (int r = 0; r < 4; r++) {
        int k = k0 + threadIdx.y + r * 8;
        tile[threadIdx.y + r * 8][threadIdx.x] =
            W[boff + (size_t)k * N + n0 + threadIdx.x];
    }
    __syncthreads();
#pragma unroll
    for (int r = 0; r < 4; r++) {
        int n = n0 + threadIdx.y + r * 8;
        T[boff + (size_t)n * K + k0 + threadIdx.x] =
            __float2half(tile[threadIdx.x][threadIdx.y + r * 8]);
    }
}

// ---------------- launch ------------------------------------------------------
extern "C" void kernel_launch(void* const* d_in, const int* in_sizes, int n_in,
                              void* d_out, int out_size)
{
    const float* x     = (const float*)d_in[0];
    const int*   li    = (const int*)  d_in[1];
    const float* mlp_w = (const float*)d_in[2];
    const float* mlp_b = (const float*)d_in[3];
    const float* bg    = (const float*)d_in[4];
    const float* ln1g  = (const float*)d_in[5];
    const float* ln1b  = (const float*)d_in[6];
    const float* wq    = (const float*)d_in[7];
    const float* bq    = (const float*)d_in[8];
    const float* wk    = (const float*)d_in[9];
    const float* bk    = (const float*)d_in[10];
    const float* wv    = (const float*)d_in[11];
    const float* bv    = (const float*)d_in[12];
    const float* wo    = (const float*)d_in[13];
    const float* bo    = (const float*)d_in[14];
    const float* ln2g  = (const float*)d_in[15];
    const float* ln2b  = (const float*)d_in[16];
    const float* w1    = (const float*)d_in[17];
    const float* b1    = (const float*)d_in[18];
    const float* w2    = (const float*)d_in[19];
    const float* b2    = (const float*)d_in[20];
    const float* pw    = (const float*)d_in[21];
    const float* pb    = (const float*)d_in[22];
    float* out = (float*)d_out;
    (void)in_sizes; (void)n_in; (void)out_size;

    float *ptrx;
    __half *pA, *pB, *pC, *pK, *pV, *pW;
    int *pcnt;
    cudaGetSymbolAddress((void**)&ptrx, g_trx);
    cudaGetSymbolAddress((void**)&pA,   g_ah);
    cudaGetSymbolAddress((void**)&pB,   g_bh);
    cudaGetSymbolAddress((void**)&pC,   g_ch);
    cudaGetSymbolAddress((void**)&pK,   g_kh);
    cudaGetSymbolAddress((void**)&pV,   g_vh);
    cudaGetSymbolAddress((void**)&pW,   g_wh);
    cudaGetSymbolAddress((void**)&pcnt, g_cnt);

    cudaFuncSetAttribute(k_gemm_h, cudaFuncAttributeMaxDynamicSharedMemorySize,
                         GEMM_SMEM_H);

    // --- weight transpose+convert (deterministic, every call) ---
    dim3 wb(32, 8);
    k_wt<<<dim3(8, 8, 3),   wb>>>(mlp_w, pW + OFF_MLPW, 256, 256);
    k_wt<<<dim3(8, 8, 8),   wb>>>(wq,    pW + OFF_WQ,   256, 256);
    k_wt<<<dim3(8, 8, 8),   wb>>>(wk,    pW + OFF_WK,   256, 256);
    k_wt<<<dim3(8, 8, 8),   wb>>>(wv,    pW + OFF_WV,   256, 256);
    k_wt<<<dim3(8, 8, 8),   wb>>>(wo,    pW + OFF_WO,   256, 256);
    k_wt<<<dim3(32, 8, 8),  wb>>>(w1,    pW + OFF_W1,   256, 1024);
    k_wt<<<dim3(8, 32, 8),  wb>>>(w2,    pW + OFF_W2,   1024, 256);
    k_wt<<<dim3(16, 64, 1), wb>>>(pw,    pW + OFF_PROJ, 2048, 512);

    auto gemm = [&](const __half* A, int woff, const float* bias,
                    const float* res, const int* gate,
                    float* Cf, __half* Ch, int M, int N, int K, int act) {
        dim3 grid(N / 128, (M + 127) / 128);
        k_gemm_h<<<grid, 256, GEMM_SMEM_H>>>(A, pW + woff, bias, res, gate,
                                             Cf, Ch, M, N, K, act);
    };

    // --- obs feature MLP: fc1 -> gelu -> fc2 -> gelu -> fc3 ---
    k_tohalf<<<(NOBS * DIM / 4 + 255) / 256, 256>>>((const float4*)x, pB, NOBS * DIM / 4);
    gemm(pB, OFF_MLPW,             mlp_b,       nullptr, nullptr, nullptr, pA, NOBS, DIM, DIM, 1);
    gemm(pA, OFF_MLPW + 65536,     mlp_b + 256, nullptr, nullptr, nullptr, pB, NOBS, DIM, DIM, 1);
    gemm(pB, OFF_MLPW + 2 * 65536, mlp_b + 512, nullptr, nullptr, nullptr, pA, NOBS, DIM, DIM, 0);

    // --- dispatch into buckets ---
    k_reset_cnt<<<(NBUK + 255) / 256, 256>>>();
    k_flatpos<<<(NOBS + 255) / 256, 256>>>(li);
    k_scatter<<<NOBS / 8, 256>>>(pA);
    k_init_trx<<<NOBS * DIM / 4 / 256, 256>>>(bg);

    // --- batched K/V for all 8 layers (ctx is layer-invariant) ---
    gemm(pC, OFF_WK, bk, nullptr, nullptr, nullptr, pK, NOBS, DIM * DEPTH, DIM, 0);
    gemm(pC, OFF_WV, bv, nullptr, nullptr, nullptr, pV, NOBS, DIM * DEPTH, DIM, 0);

    // --- 8-layer cross-attention transformer ---
    for (int l = 0; l < DEPTH; l++) {
        k_ln<<<NBUK, 256>>>(ptrx, pB, ln1g + l * DIM, ln1b + l * DIM);
        gemm(pB, OFF_WQ + l * 65536, bq + l * DIM, nullptr, nullptr,
             nullptr, pA, NOBS, DIM, DIM, 0);
        k_attn<<<NBUK, 64>>>(pA, pK, pV, pB, l * DIM);
        gemm(pB, OFF_WO + l * 65536, bo + l * DIM, ptrx, nullptr,
             ptrx, nullptr, NOBS, DIM, DIM, 0);
        k_ln<<<NBUK, 256>>>(ptrx, pB, ln2g + l * DIM, ln2b + l * DIM);

        // FFN, L2-blocked over M: intermediate chunk (24000x1024 half = 49MB)
        // stays L2-resident between the w1 and w2 launches.
        for (int c = 0; c < NOBS / MCHUNK; c++) {
            size_t ofD = (size_t)c * MCHUNK * DIM;
            size_t ofF = (size_t)c * MCHUNK * FFND;
            gemm(pB + ofD, OFF_W1 + l * DIM * FFND, b1 + l * FFND, nullptr, nullptr,
                 nullptr, pA + ofF, MCHUNK, FFND, DIM, 1);
            if (l < DEPTH - 1) {
                gemm(pA + ofF, OFF_W2 + l * FFND * DIM, b2 + l * DIM, ptrx + ofD,
                     nullptr, ptrx + ofD, nullptr, MCHUNK, DIM, FFND, 0);
            } else {
                // last layer: emit half; [72000,256] half == [9000,2048] half
                gemm(pA + ofF, OFF_W2 + l * FFND * DIM, b2 + l * DIM, ptrx + ofD,
                     nullptr, nullptr, pB + ofD, MCHUNK, DIM, FFND, 0);
            }
        }
    }

    // --- final projection, gated by occupancy ---
    gemm(pB, OFF_PROJ, pb, nullptr, pcnt, out, nullptr, NBUK, CLAT, OUTD, 0);
}